// round 16
// baseline (speedup 1.0000x reference)
#include <cuda_runtime.h>
#include <cuda_bf16.h>
#include <cstdint>

// pooled[i][j] = 1.0 if any k in [j-25, j+25] (in-range) has |in[i]-w[k]| < 0.1
// N=1024, M=262144 -> 1 GiB fp32 output; at the HBM write ceiling (~7 TB/s).
//
// R16 = R11 (best, 145.9us, DRAM 89%) with the emit widened to 32B stores:
// each lane writes one aligned ulonglong4 (8 floats) per step -> 2 emit
// shuffles + 4 wide stores per row-pair (was 4 + 8). ptxas emits STG.256 on
// sm_103a if profitable, else splits to 2x STG.128 (== R11 behavior), so
// this probe has no downside. Everything else unchanged and A/B-justified:
//  - warp-independent 512-col segments, no smem, no block barriers (R6)
//  - 16 weights/thread as negated packed f32x2 pairs (R10)
//  - mask bit = sign(fma(d,d,-0.01)) via funnel shifts (R5)
//  - two rows packed per 32-bit word (R11)
//  - width-51 sliding-OR via two 64-bit log-step dilations
//  - ROWS_PER_BLOCK=8, grid 8192, 5 blocks/SM (R13/R14)

#define THREADS 256
#define WPT 16                       // pooled bits per thread
#define SEG 512                      // columns per warp
#define CHUNK (THREADS * WPT)        // 4096 columns per block
#define ROWS_PER_BLOCK 8
#define THRESH 0.1f
#define OOR_VAL 3.0e38f              // sentinel == -inf pad (never within 0.1)

// mask bit b (0..15) = (vi - w[b])^2 < 0.01
__device__ __forceinline__ unsigned mask16_sq(unsigned long long vv,
                                              const unsigned long long* nwp,
                                              unsigned long long c2)
{
    unsigned m = 0;
    #pragma unroll
    for (int k = 7; k >= 0; --k) {
        unsigned long long d, s;
        asm("add.rn.f32x2 %0, %1, %2;" : "=l"(d) : "l"(vv), "l"(nwp[k]));
        asm("fma.rn.f32x2 %0, %1, %1, %2;" : "=l"(s) : "l"(d), "l"(c2));
        m = __funnelshift_l((unsigned)(s >> 32), m, 1);   // weight 2k+1
        m = __funnelshift_l((unsigned)s,         m, 1);   // weight 2k
    }
    return m & 0xFFFFu;
}

// expand 8 mask bits into 8 packed fp32 (1.0f / 0.0f) as a ulonglong4
__device__ __forceinline__ ulonglong4 expand8(unsigned bits)
{
    const unsigned f0 = (bits &   1u) * 0x3F800000u;
    const unsigned f1 = (bits &   2u) * 0x1FC00000u;
    const unsigned f2 = (bits &   4u) * 0x0FE00000u;
    const unsigned f3 = (bits &   8u) * 0x07F00000u;
    const unsigned f4 = (bits &  16u) * 0x03F80000u;
    const unsigned f5 = (bits &  32u) * 0x01FC0000u;
    const unsigned f6 = (bits &  64u) * 0x00FE0000u;
    const unsigned f7 = (bits & 128u) * 0x007F0000u;
    ulonglong4 v;
    v.x = (unsigned long long)f0 | ((unsigned long long)f1 << 32);
    v.y = (unsigned long long)f2 | ((unsigned long long)f3 << 32);
    v.z = (unsigned long long)f4 | ((unsigned long long)f5 << 32);
    v.w = (unsigned long long)f6 | ((unsigned long long)f7 << 32);
    return v;
}

__global__ __launch_bounds__(THREADS, 5)
void cll_pool_kernel(const float* __restrict__ in_feat,
                     const float* __restrict__ weights,
                     float* __restrict__ out,
                     int N, int M)
{
    const int t = threadIdx.x;
    const int lane = t & 31;
    const int warp = t >> 5;
    const int segbase = blockIdx.x * CHUNK + warp * SEG;

    // ---- one-time: this thread's 16 weights -> 8 packed negated pairs ----
    unsigned long long nwp[8];
    {
        const int g0 = segbase + lane * WPT;
        float wv[16];
        if (g0 + WPT <= M) {
            const float4* wp = reinterpret_cast<const float4*>(weights + g0);
            #pragma unroll
            for (int g = 0; g < 4; ++g) {
                float4 q = wp[g];
                wv[4*g+0] = q.x; wv[4*g+1] = q.y; wv[4*g+2] = q.z; wv[4*g+3] = q.w;
            }
        } else {
            #pragma unroll
            for (int b = 0; b < 16; ++b) {
                int gg = g0 + b;
                wv[b] = (gg < M) ? weights[gg] : OOR_VAL;
            }
        }
        #pragma unroll
        for (int k = 0; k < 8; ++k) {
            unsigned lo = __float_as_uint(-wv[2*k]);
            unsigned hi = __float_as_uint(-wv[2*k+1]);
            nwp[k] = ((unsigned long long)hi << 32) | lo;
        }
    }
    // per-lane halo weights (32 cols each side of segment)
    float hwl, hwr;
    {
        int gl = segbase - 32 + lane;
        int gr = segbase + SEG + lane;
        hwl = (gl >= 0 && gl < M) ? __ldg(weights + gl) : OOR_VAL;
        hwr = (gr < M)            ? __ldg(weights + gr) : OOR_VAL;
    }

    const unsigned long long c2 =
        ((unsigned long long)__float_as_uint(-0.01f) << 32) | __float_as_uint(-0.01f);

    const int row0 = blockIdx.y * ROWS_PER_BLOCK;
    const int shamt8 = (lane & 1) * 8;         // byte half within owner's 16-bit word
    const int srcbase = lane >> 1;             // owner lane offset within emit step

    #pragma unroll 1
    for (int r = 0; r < ROWS_PER_BLOCK; r += 2) {
        int i0 = row0 + r;     if (i0 >= N) i0 = N - 1;
        int i1 = row0 + r + 1; if (i1 >= N) i1 = N - 1;
        const float v0 = __ldg(&in_feat[i0]);
        const float v1 = __ldg(&in_feat[i1]);

        // ---- two 16-bit mask words, packed ----
        const unsigned long long vv0 =
            ((unsigned long long)__float_as_uint(v0) << 32) | __float_as_uint(v0);
        const unsigned long long vv1 =
            ((unsigned long long)__float_as_uint(v1) << 32) | __float_as_uint(v1);
        const unsigned mm = mask16_sq(vv0, nwp, c2) | (mask16_sq(vv1, nwp, c2) << 16);

        const unsigned hl0 = __ballot_sync(0xFFFFFFFFu, fabsf(v0 - hwl) < THRESH);
        const unsigned hr0 = __ballot_sync(0xFFFFFFFFu, fabsf(v0 - hwr) < THRESH);
        const unsigned hl1 = __ballot_sync(0xFFFFFFFFu, fabsf(v1 - hwl) < THRESH);
        const unsigned hr1 = __ballot_sync(0xFFFFFFFFu, fabsf(v1 - hwr) < THRESH);

        // ---- ONE set of neighbor shuffles for both rows ----
        unsigned wm1 = __shfl_up_sync(0xFFFFFFFFu, mm, 1);
        unsigned wm2 = __shfl_up_sync(0xFFFFFFFFu, mm, 2);
        unsigned wp1 = __shfl_down_sync(0xFFFFFFFFu, mm, 1);
        unsigned wp2 = __shfl_down_sync(0xFFFFFFFFu, mm, 2);
        if (lane == 0) {
            wm1 = (hl0 >> 16) | (hl1 & 0xFFFF0000u);
            wm2 = (hl0 & 0xFFFFu) | (hl1 << 16);
        }
        if (lane == 1)  { wm2 = (hl0 >> 16) | (hl1 & 0xFFFF0000u); }
        if (lane == 31) {
            wp1 = (hr0 & 0xFFFFu) | (hr1 << 16);
            wp2 = (hr0 >> 16) | (hr1 & 0xFFFF0000u);
        }
        if (lane == 30) { wp2 = (hr0 & 0xFFFFu) | (hr1 << 16); }

        // ---- per-row dilation, pooled words packed ----
        unsigned pp = 0;
        #pragma unroll
        for (int x = 0; x < 2; ++x) {
            const unsigned a2 = (wm2 >> (16 * x)) & 0xFFFFu;
            const unsigned a1 = (wm1 >> (16 * x)) & 0xFFFFu;
            const unsigned a0 = (mm  >> (16 * x)) & 0xFFFFu;
            const unsigned b1 = (wp1 >> (16 * x)) & 0xFFFFu;
            const unsigned b2 = (wp2 >> (16 * x)) & 0xFFFFu;
            unsigned long long lo =  (unsigned long long)a2
                                  | ((unsigned long long)a1 << 16)
                                  | ((unsigned long long)a0 << 32)
                                  | ((unsigned long long)b1 << 48);
            unsigned long long hi =  (unsigned long long)a1
                                  | ((unsigned long long)a0 << 16)
                                  | ((unsigned long long)b1 << 32)
                                  | ((unsigned long long)b2 << 48);
            hi |= hi >> 1;  hi |= hi >> 2;  hi |= hi >> 4;  hi |= hi >> 8;  hi |= hi >> 10;
            lo |= lo << 1;  lo |= lo << 2;  lo |= lo << 4;  lo |= lo << 8;  lo |= lo << 10;
            const unsigned p = ((unsigned)(lo >> 32) | (unsigned)(hi >> 16)) & 0xFFFFu;
            pp |= p << (16 * x);
        }

        // ---- emit: 2 shuffles, each lane stores 32B per row ----
        // step s covers cols [s*256, s*256+256): lane t writes cols s*256 + t*8,
        // sourced from lane (s*16 + t/2)'s pooled word, byte half (t%2).
        float* w0 = out + (size_t)i0 * (size_t)M + segbase;
        float* w1 = out + (size_t)i1 * (size_t)M + segbase;
        #pragma unroll
        for (int s = 0; s < 2; ++s) {
            const unsigned src = __shfl_sync(0xFFFFFFFFu, pp, s * 16 + srcbase);
            const ulonglong4 q0 = expand8((src >> shamt8) & 0xFFu);          // row i0
            const ulonglong4 q1 = expand8((src >> (16 + shamt8)) & 0xFFu);   // row i1
            reinterpret_cast<ulonglong4*>(w0 + s * 256)[lane] = q0;
            reinterpret_cast<ulonglong4*>(w1 + s * 256)[lane] = q1;
        }
    }
}

extern "C" void kernel_launch(void* const* d_in, const int* in_sizes, int n_in,
                              void* d_out, int out_size)
{
    const float* in_feat = (const float*)d_in[0];   // 1024 elements
    const float* weights = (const float*)d_in[1];   // 262144 elements
    float* out = (float*)d_out;

    const int N = in_sizes[0];
    const int M = in_sizes[1];

    dim3 grid((M + CHUNK - 1) / CHUNK, (N + ROWS_PER_BLOCK - 1) / ROWS_PER_BLOCK);
    cll_pool_kernel<<<grid, THREADS>>>(in_feat, weights, out, N, M);
}

// round 17
// speedup vs baseline: 1.7902x; 1.7902x over previous
#include <cuda_runtime.h>
#include <cuda_bf16.h>
#include <cstdint>

// pooled[i][j] = 1.0 if any k in [j-25, j+25] (in-range) has |in[i]-w[k]| < 0.1
// N=1024, M=262144 -> 1 GiB fp32 output.
//
// FINAL (= R11, measured best 145.9us, 7.0 TB/s = 88% of HBM spec on a pure
// write stream — the practical write roofline). Every element justified by
// an isolated A/B across R1-R16:
//  - warp-independent 512-col segments, zero smem, zero block barriers (R6)
//  - 16 weights/thread in registers as negated packed f32x2 pairs
//    (R10; WPT=32 starves occupancy, WPT=8 doubles ALU -> both slower)
//  - mask bit = sign(fma(d,d,-0.01)) streamed via funnel shifts (R5)
//  - two rows packed per 32-bit word: one set of neighbor+emit shuffles
//    serves both rows (R11; 4-row packing regressed on ALU)
//  - width-51 sliding-OR via two 64-bit log-step dilations
//  - dense shuffle-redistributed STG.128 stores, lane*16B within 512B warp
//    steps — the ONLY store shape that sustains the write roofline here
//    (per-thread-contig: 2.7x slower; 32B interleave: 1.4x; 32B/lane: 1.8x)
//  - ROWS_PER_BLOCK=8, grid 8192, 5 blocks/SM (R13/R14: 6 blocks and
//    16 rows both regress; persistent grids lose to wave-stealing)

#define THREADS 256
#define WPT 16                       // pooled bits per thread
#define SEG 512                      // columns per warp
#define CHUNK (THREADS * WPT)        // 4096 columns per block
#define ROWS_PER_BLOCK 8
#define THRESH 0.1f
#define OOR_VAL 3.0e38f              // sentinel == -inf pad (never within 0.1)

// mask bit b (0..15) = (vi - w[b])^2 < 0.01
__device__ __forceinline__ unsigned mask16_sq(unsigned long long vv,
                                              const unsigned long long* nwp,
                                              unsigned long long c2)
{
    unsigned m = 0;
    #pragma unroll
    for (int k = 7; k >= 0; --k) {
        unsigned long long d, s;
        asm("add.rn.f32x2 %0, %1, %2;" : "=l"(d) : "l"(vv), "l"(nwp[k]));
        asm("fma.rn.f32x2 %0, %1, %1, %2;" : "=l"(s) : "l"(d), "l"(c2));
        m = __funnelshift_l((unsigned)(s >> 32), m, 1);   // weight 2k+1
        m = __funnelshift_l((unsigned)s,         m, 1);   // weight 2k
    }
    return m & 0xFFFFu;
}

__global__ __launch_bounds__(THREADS, 5)
void cll_pool_kernel(const float* __restrict__ in_feat,
                     const float* __restrict__ weights,
                     float* __restrict__ out,
                     int N, int M)
{
    const int t = threadIdx.x;
    const int lane = t & 31;
    const int warp = t >> 5;
    const int segbase = blockIdx.x * CHUNK + warp * SEG;

    // ---- one-time: this thread's 16 weights -> 8 packed negated pairs ----
    unsigned long long nwp[8];
    {
        const int g0 = segbase + lane * WPT;
        float wv[16];
        if (g0 + WPT <= M) {
            const float4* wp = reinterpret_cast<const float4*>(weights + g0);
            #pragma unroll
            for (int g = 0; g < 4; ++g) {
                float4 q = wp[g];
                wv[4*g+0] = q.x; wv[4*g+1] = q.y; wv[4*g+2] = q.z; wv[4*g+3] = q.w;
            }
        } else {
            #pragma unroll
            for (int b = 0; b < 16; ++b) {
                int gg = g0 + b;
                wv[b] = (gg < M) ? weights[gg] : OOR_VAL;
            }
        }
        #pragma unroll
        for (int k = 0; k < 8; ++k) {
            unsigned lo = __float_as_uint(-wv[2*k]);
            unsigned hi = __float_as_uint(-wv[2*k+1]);
            nwp[k] = ((unsigned long long)hi << 32) | lo;
        }
    }
    // per-lane halo weights (32 cols each side of segment)
    float hwl, hwr;
    {
        int gl = segbase - 32 + lane;
        int gr = segbase + SEG + lane;
        hwl = (gl >= 0 && gl < M) ? __ldg(weights + gl) : OOR_VAL;
        hwr = (gr < M)            ? __ldg(weights + gr) : OOR_VAL;
    }

    const unsigned long long c2 =
        ((unsigned long long)__float_as_uint(-0.01f) << 32) | __float_as_uint(-0.01f);

    const int row0 = blockIdx.y * ROWS_PER_BLOCK;
    const int shamt = (lane & 3) * 4;
    const int srcbase = lane >> 2;

    #pragma unroll 1
    for (int r = 0; r < ROWS_PER_BLOCK; r += 2) {
        int i0 = row0 + r;     if (i0 >= N) i0 = N - 1;
        int i1 = row0 + r + 1; if (i1 >= N) i1 = N - 1;
        const float v0 = __ldg(&in_feat[i0]);
        const float v1 = __ldg(&in_feat[i1]);

        // ---- two 16-bit mask words, packed ----
        const unsigned long long vv0 =
            ((unsigned long long)__float_as_uint(v0) << 32) | __float_as_uint(v0);
        const unsigned long long vv1 =
            ((unsigned long long)__float_as_uint(v1) << 32) | __float_as_uint(v1);
        const unsigned mm = mask16_sq(vv0, nwp, c2) | (mask16_sq(vv1, nwp, c2) << 16);

        const unsigned hl0 = __ballot_sync(0xFFFFFFFFu, fabsf(v0 - hwl) < THRESH);
        const unsigned hr0 = __ballot_sync(0xFFFFFFFFu, fabsf(v0 - hwr) < THRESH);
        const unsigned hl1 = __ballot_sync(0xFFFFFFFFu, fabsf(v1 - hwl) < THRESH);
        const unsigned hr1 = __ballot_sync(0xFFFFFFFFu, fabsf(v1 - hwr) < THRESH);

        // ---- ONE set of neighbor shuffles for both rows ----
        unsigned wm1 = __shfl_up_sync(0xFFFFFFFFu, mm, 1);
        unsigned wm2 = __shfl_up_sync(0xFFFFFFFFu, mm, 2);
        unsigned wp1 = __shfl_down_sync(0xFFFFFFFFu, mm, 1);
        unsigned wp2 = __shfl_down_sync(0xFFFFFFFFu, mm, 2);
        if (lane == 0) {
            wm1 = (hl0 >> 16) | (hl1 & 0xFFFF0000u);
            wm2 = (hl0 & 0xFFFFu) | (hl1 << 16);
        }
        if (lane == 1)  { wm2 = (hl0 >> 16) | (hl1 & 0xFFFF0000u); }
        if (lane == 31) {
            wp1 = (hr0 & 0xFFFFu) | (hr1 << 16);
            wp2 = (hr0 >> 16) | (hr1 & 0xFFFF0000u);
        }
        if (lane == 30) { wp2 = (hr0 & 0xFFFFu) | (hr1 << 16); }

        // ---- per-row dilation, pooled words packed ----
        unsigned pp = 0;
        #pragma unroll
        for (int x = 0; x < 2; ++x) {
            const unsigned a2 = (wm2 >> (16 * x)) & 0xFFFFu;
            const unsigned a1 = (wm1 >> (16 * x)) & 0xFFFFu;
            const unsigned a0 = (mm  >> (16 * x)) & 0xFFFFu;
            const unsigned b1 = (wp1 >> (16 * x)) & 0xFFFFu;
            const unsigned b2 = (wp2 >> (16 * x)) & 0xFFFFu;
            unsigned long long lo =  (unsigned long long)a2
                                  | ((unsigned long long)a1 << 16)
                                  | ((unsigned long long)a0 << 32)
                                  | ((unsigned long long)b1 << 48);
            unsigned long long hi =  (unsigned long long)a1
                                  | ((unsigned long long)a0 << 16)
                                  | ((unsigned long long)b1 << 32)
                                  | ((unsigned long long)b2 << 48);
            hi |= hi >> 1;  hi |= hi >> 2;  hi |= hi >> 4;  hi |= hi >> 8;  hi |= hi >> 10;
            lo |= lo << 1;  lo |= lo << 2;  lo |= lo << 4;  lo |= lo << 8;  lo |= lo << 10;
            const unsigned p = ((unsigned)(lo >> 32) | (unsigned)(hi >> 16)) & 0xFFFFu;
            pp |= p << (16 * x);
        }

        // ---- emit: ONE set of 4 shuffles feeds both rows' dense stores ----
        float* w0 = out + (size_t)i0 * (size_t)M + segbase;
        float* w1 = out + (size_t)i1 * (size_t)M + segbase;
        #pragma unroll
        for (int s = 0; s < 4; ++s) {
            const unsigned src = __shfl_sync(0xFFFFFFFFu, pp, s * 8 + srcbase);
            const unsigned b0 = src >> shamt;          // row i0 nibble
            const unsigned b1 = src >> (shamt + 16);   // row i1 nibble
            float4 q0, q1;
            q0.x = __uint_as_float((b0 & 1u) * 0x3F800000u);
            q0.y = __uint_as_float((b0 & 2u) * 0x1FC00000u);
            q0.z = __uint_as_float((b0 & 4u) * 0x0FE00000u);
            q0.w = __uint_as_float((b0 & 8u) * 0x07F00000u);
            q1.x = __uint_as_float((b1 & 1u) * 0x3F800000u);
            q1.y = __uint_as_float((b1 & 2u) * 0x1FC00000u);
            q1.z = __uint_as_float((b1 & 4u) * 0x0FE00000u);
            q1.w = __uint_as_float((b1 & 8u) * 0x07F00000u);
            __stcs(reinterpret_cast<float4*>(w0 + s * 128) + lane, q0);
            __stcs(reinterpret_cast<float4*>(w1 + s * 128) + lane, q1);
        }
    }
}

extern "C" void kernel_launch(void* const* d_in, const int* in_sizes, int n_in,
                              void* d_out, int out_size)
{
    const float* in_feat = (const float*)d_in[0];   // 1024 elements
    const float* weights = (const float*)d_in[1];   // 262144 elements
    float* out = (float*)d_out;

    const int N = in_sizes[0];
    const int M = in_sizes[1];

    dim3 grid((M + CHUNK - 1) / CHUNK, (N + ROWS_PER_BLOCK - 1) / ROWS_PER_BLOCK);
    cll_pool_kernel<<<grid, THREADS>>>(in_feat, weights, out, N, M);
}